// round 1
// baseline (speedup 1.0000x reference)
#include <cuda_runtime.h>
#include <cuda_bf16.h>
#include <math.h>

#define NV 50000
#define EE 800000
#define ET (EE + NV)        // 850000 edges incl. self loops
#define FIN 256
#define HID 64
#define HEADS 4
#define D1 (HEADS * HID)    // 256

// ---------------- scratch (device globals; no allocations allowed) ----------
__device__ float    g_xh1[NV * D1];       // layer1 transformed features, then reused as h (elu output)
__device__ float    g_out1[NV * D1];      // layer1 aggregation accumulator
__device__ float    g_als1[NV * HEADS];
__device__ float    g_ald1[NV * HEADS];
__device__ unsigned g_max1[NV * HEADS];
__device__ float    g_den1[NV * HEADS];
__device__ float    g_ex1[ET * HEADS];

__device__ float    g_xh2[NV * HID];
__device__ float    g_out2[NV * HID];
__device__ float    g_als2[NV];
__device__ float    g_ald2[NV];
__device__ unsigned g_max2[NV];
__device__ float    g_den2[NV];
__device__ float    g_ex2[ET];

// ---------------- helpers ----------------------------------------------------
__device__ __forceinline__ unsigned enc_f(float f) {
    unsigned u = __float_as_uint(f);
    return (u & 0x80000000u) ? ~u : (u | 0x80000000u);
}
__device__ __forceinline__ float dec_f(unsigned u) {
    return (u & 0x80000000u) ? __uint_as_float(u & 0x7FFFFFFFu)
                             : __uint_as_float(~u);
}
__device__ __forceinline__ float lrelu(float v) { return v > 0.f ? v : 0.2f * v; }

__device__ __forceinline__ void edge_sd(const int* __restrict__ ei, int e, int& s, int& d) {
    if (e < EE) { s = ei[e]; d = ei[EE + e]; }
    else        { s = e - EE; d = s; }
}

// ---------------- init ------------------------------------------------------
__global__ void init_all() {
    int i = blockIdx.x * blockDim.x + threadIdx.x;
    if (i < NV * D1) g_out1[i] = 0.f;
    if (i < NV * HID) g_out2[i] = 0.f;
    if (i < NV * HEADS) { g_den1[i] = 0.f; g_max1[i] = 0u; }
    if (i < NV) { g_den2[i] = 0.f; g_max2[i] = 0u; }
}

// ---------------- SGEMM: C[M,N] = A[M,K] @ B[K,N], fp32, 64x64 tile ----------
__global__ void sgemm64(const float* __restrict__ A, const float* __restrict__ B,
                        float* __restrict__ C, int M, int N, int K) {
    __shared__ float As[16][64];
    __shared__ float Bs[16][64];
    int tid = threadIdx.x;
    int tx = tid & 15, ty = tid >> 4;
    int rowBase = blockIdx.y * 64, colBase = blockIdx.x * 64;
    float acc[4][4] = {};
    for (int k0 = 0; k0 < K; k0 += 16) {
#pragma unroll
        for (int i = 0; i < 4; i++) {
            int idx = tid + i * 256;
            int r = idx >> 4, c = idx & 15;
            int gr = rowBase + r;
            As[c][r] = (gr < M) ? A[gr * K + k0 + c] : 0.f;
        }
#pragma unroll
        for (int i = 0; i < 4; i++) {
            int idx = tid + i * 256;
            int r = idx >> 6, c = idx & 63;
            Bs[r][c] = B[(k0 + r) * N + colBase + c];
        }
        __syncthreads();
#pragma unroll
        for (int k = 0; k < 16; k++) {
            float a[4], b[4];
#pragma unroll
            for (int m = 0; m < 4; m++) a[m] = As[k][ty * 4 + m];
#pragma unroll
            for (int n = 0; n < 4; n++) b[n] = Bs[k][tx * 4 + n];
#pragma unroll
            for (int m = 0; m < 4; m++)
#pragma unroll
                for (int n = 0; n < 4; n++) acc[m][n] += a[m] * b[n];
        }
        __syncthreads();
    }
#pragma unroll
    for (int m = 0; m < 4; m++) {
        int gr = rowBase + ty * 4 + m;
        if (gr >= M) continue;
#pragma unroll
        for (int n = 0; n < 4; n++) C[gr * N + colBase + tx * 4 + n] = acc[m][n];
    }
}

// ---------------- attention dots: warp per (node,head), C=64 -----------------
__global__ void attn_dots(const float* __restrict__ xh, const float* __restrict__ asrc,
                          const float* __restrict__ adst, float* __restrict__ als,
                          float* __restrict__ ald, int NH, int H) {
    int w = (blockIdx.x * blockDim.x + threadIdx.x) >> 5;
    if (w >= NH) return;
    int lane = threadIdx.x & 31;
    int h = w % H;
    const float* row = xh + (size_t)w * 64;
    float x0 = row[lane], x1 = row[lane + 32];
    float s = x0 * asrc[h * 64 + lane] + x1 * asrc[h * 64 + lane + 32];
    float d = x0 * adst[h * 64 + lane] + x1 * adst[h * 64 + lane + 32];
#pragma unroll
    for (int o = 16; o; o >>= 1) {
        s += __shfl_down_sync(0xFFFFFFFFu, s, o);
        d += __shfl_down_sync(0xFFFFFFFFu, d, o);
    }
    if (lane == 0) { als[w] = s; ald[w] = d; }
}

// ---------------- edge pass 1: segment max -----------------------------------
template <int H>
__global__ void edge_max_k(const int* __restrict__ ei, const float* __restrict__ als,
                           const float* __restrict__ ald, unsigned* __restrict__ mx) {
    int e = blockIdx.x * blockDim.x + threadIdx.x;
    if (e >= ET) return;
    int s, d; edge_sd(ei, e, s, d);
#pragma unroll
    for (int h = 0; h < H; h++) {
        float v = lrelu(als[s * H + h] + ald[d * H + h]);
        atomicMax(&mx[d * H + h], enc_f(v));
    }
}

// ---------------- edge pass 2: exp + denominator -----------------------------
template <int H>
__global__ void edge_exp_k(const int* __restrict__ ei, const float* __restrict__ als,
                           const float* __restrict__ ald, const unsigned* __restrict__ mx,
                           float* __restrict__ den, float* __restrict__ ex) {
    int e = blockIdx.x * blockDim.x + threadIdx.x;
    if (e >= ET) return;
    int s, d; edge_sd(ei, e, s, d);
#pragma unroll
    for (int h = 0; h < H; h++) {
        float v = lrelu(als[s * H + h] + ald[d * H + h]);
        float m = dec_f(mx[d * H + h]);
        float t = expf(v - m);
        ex[(size_t)e * H + h] = t;
        atomicAdd(&den[d * H + h], t);
    }
}

// ---------------- edge pass 3: weighted aggregation (warp per edge) ----------
template <int H>
__global__ void edge_aggr_k(const int* __restrict__ ei, const float* __restrict__ ex,
                            const float* __restrict__ den, const float* __restrict__ xh,
                            float* __restrict__ out) {
    int w = (blockIdx.x * blockDim.x + threadIdx.x) >> 5;
    if (w >= ET) return;
    int lane = threadIdx.x & 31;
    int s, d; edge_sd(ei, w, s, d);
    float wt[H];
#pragma unroll
    for (int h = 0; h < H; h++)
        wt[h] = ex[(size_t)w * H + h] / (den[d * H + h] + 1e-16f);
    const int C = H * 64;
#pragma unroll
    for (int it = 0; it < C / 32; it++) {
        int c = lane + it * 32;
        float v = wt[it >> 1] * xh[(size_t)s * C + c];
        atomicAdd(&out[(size_t)d * C + c], v);
    }
}

// ---------------- bias + elu --------------------------------------------------
__global__ void bias_elu(const float* __restrict__ in, const float* __restrict__ b,
                         float* __restrict__ out, int n, int bmask) {
    int i = blockIdx.x * blockDim.x + threadIdx.x;
    if (i >= n) return;
    float v = in[i] + b[i & bmask];
    out[i] = v > 0.f ? v : expm1f(v);
}

// ---------------- launch -------------------------------------------------------
extern "C" void kernel_launch(void* const* d_in, const int* in_sizes, int n_in,
                              void* d_out, int out_size) {
    const float* x     = (const float*)d_in[0];
    const int*   ei    = (const int*)d_in[1];
    const float* W1    = (const float*)d_in[2];
    const float* asrc1 = (const float*)d_in[3];
    const float* adst1 = (const float*)d_in[4];
    const float* b1    = (const float*)d_in[5];
    const float* W2    = (const float*)d_in[6];
    const float* asrc2 = (const float*)d_in[7];
    const float* adst2 = (const float*)d_in[8];
    const float* b2    = (const float*)d_in[9];
    float* out = (float*)d_out;

    float *xh1, *out1, *als1, *ald1, *den1, *ex1;
    unsigned *max1;
    float *xh2, *out2, *als2, *ald2, *den2, *ex2;
    unsigned *max2;
    cudaGetSymbolAddress((void**)&xh1,  g_xh1);
    cudaGetSymbolAddress((void**)&out1, g_out1);
    cudaGetSymbolAddress((void**)&als1, g_als1);
    cudaGetSymbolAddress((void**)&ald1, g_ald1);
    cudaGetSymbolAddress((void**)&max1, g_max1);
    cudaGetSymbolAddress((void**)&den1, g_den1);
    cudaGetSymbolAddress((void**)&ex1,  g_ex1);
    cudaGetSymbolAddress((void**)&xh2,  g_xh2);
    cudaGetSymbolAddress((void**)&out2, g_out2);
    cudaGetSymbolAddress((void**)&als2, g_als2);
    cudaGetSymbolAddress((void**)&ald2, g_ald2);
    cudaGetSymbolAddress((void**)&max2, g_max2);
    cudaGetSymbolAddress((void**)&den2, g_den2);
    cudaGetSymbolAddress((void**)&ex2,  g_ex2);

    const int TB = 256;

    // zero accumulators / maxima
    init_all<<<(NV * D1 + TB - 1) / TB, TB>>>();

    // ---------- layer 1 ----------
    {
        dim3 grid(D1 / 64, (NV + 63) / 64);
        sgemm64<<<grid, 256>>>(x, W1, xh1, NV, D1, FIN);
    }
    attn_dots<<<(NV * HEADS * 32 + TB - 1) / TB, TB>>>(xh1, asrc1, adst1, als1, ald1, NV * HEADS, HEADS);
    edge_max_k<HEADS><<<(ET + TB - 1) / TB, TB>>>(ei, als1, ald1, max1);
    edge_exp_k<HEADS><<<(ET + TB - 1) / TB, TB>>>(ei, als1, ald1, max1, den1, ex1);
    {
        long long threads = (long long)ET * 32;
        edge_aggr_k<HEADS><<<(unsigned)((threads + TB - 1) / TB), TB>>>(ei, ex1, den1, xh1, out1);
    }
    // h = elu(out1 + b1), stored back into g_xh1 (xh1 no longer needed)
    bias_elu<<<(NV * D1 + TB - 1) / TB, TB>>>(out1, b1, xh1, NV * D1, D1 - 1);

    // ---------- layer 2 ----------
    {
        dim3 grid(HID / 64 ? HID / 64 : 1, (NV + 63) / 64);
        sgemm64<<<grid, 256>>>(xh1, W2, xh2, NV, HID, D1);
    }
    attn_dots<<<(NV * 32 + TB - 1) / TB, TB>>>(xh2, asrc2, adst2, als2, ald2, NV, 1);
    edge_max_k<1><<<(ET + TB - 1) / TB, TB>>>(ei, als2, ald2, max2);
    edge_exp_k<1><<<(ET + TB - 1) / TB, TB>>>(ei, als2, ald2, max2, den2, ex2);
    {
        long long threads = (long long)ET * 32;
        edge_aggr_k<1><<<(unsigned)((threads + TB - 1) / TB), TB>>>(ei, ex2, den2, xh2, out2);
    }
    bias_elu<<<(NV * HID + TB - 1) / TB, TB>>>(out2, b2, out, NV * HID, HID - 1);
}

// round 2
// speedup vs baseline: 1.3496x; 1.3496x over previous
#include <cuda_runtime.h>
#include <cuda_bf16.h>
#include <math.h>

#define NV 50000
#define EE 800000
#define ET (EE + NV)        // edges incl. self loops
#define FIN 256
#define HID 64
#define HEADS 4
#define D1 (HEADS * HID)    // 256

typedef unsigned long long ull;

// ---------------- scratch -----------------------------------------------------
__device__ float g_xh1[NV * D1];
__device__ float g_h1[NV * D1];
__device__ float g_xh2[NV * HID];
__device__ float g_als1[NV * HEADS];
__device__ float g_ald1[NV * HEADS];
__device__ float g_als2[NV];
__device__ float g_ald2[NV];
__device__ int   g_rowptr[NV + 1];
__device__ int   g_deg[NV];          // degree -> cursor
__device__ int   g_elist[ET];        // src node per CSR slot

// ---------------- helpers ------------------------------------------------------
__device__ __forceinline__ float lrelu(float v) { return v > 0.f ? v : 0.2f * v; }

__device__ __forceinline__ void edge_sd(const int* __restrict__ ei, int e, int& s, int& d) {
    if (e < EE) { s = ei[e]; d = ei[EE + e]; }
    else        { s = e - EE; d = s; }
}

#define FMA2(acc, a, b) asm("fma.rn.f32x2 %0, %1, %2, %3;" : "=l"(acc) : "l"(a), "l"(b), "l"(acc))
#define PACK2(out, v)   asm("mov.b64 %0, {%1, %1};" : "=l"(out) : "r"(__float_as_uint(v)))
#define UNPACK2(lo, hi, in) asm("mov.b64 {%0, %1}, %2;" : "=r"(lo), "=r"(hi) : "l"(in))

// ---------------- CSR build ----------------------------------------------------
__global__ void deg_init() {
    int i = blockIdx.x * blockDim.x + threadIdx.x;
    if (i < NV) g_deg[i] = 1;   // self loop
}
__global__ void deg_hist(const int* __restrict__ ei) {
    int e = blockIdx.x * blockDim.x + threadIdx.x;
    if (e < EE) atomicAdd(&g_deg[ei[EE + e]], 1);
}
__global__ void scan_k() {
    __shared__ int ssum[1024];
    const int CH = (NV + 1023) / 1024;
    int t = threadIdx.x;
    int base = t * CH;
    int s = 0;
    for (int j = 0; j < CH; j++) { int i = base + j; if (i < NV) s += g_deg[i]; }
    ssum[t] = s;
    __syncthreads();
    for (int off = 1; off < 1024; off <<= 1) {
        int v = (t >= off) ? ssum[t - off] : 0;
        __syncthreads();
        ssum[t] += v;
        __syncthreads();
    }
    int off = (t == 0) ? 0 : ssum[t - 1];
    for (int j = 0; j < CH; j++) {
        int i = base + j;
        if (i < NV) {
            int d = g_deg[i];
            g_rowptr[i] = off;
            g_deg[i] = off;   // cursor
            off += d;
        }
    }
    if (t == 0) g_rowptr[NV] = ET;
}
__global__ void scatter_k(const int* __restrict__ ei) {
    int e = blockIdx.x * blockDim.x + threadIdx.x;
    if (e >= ET) return;
    int s, d; edge_sd(ei, e, s, d);
    int pos = atomicAdd(&g_deg[d], 1);
    g_elist[pos] = s;
}

// ---------------- GEMM: C[M,N] = A[M,K] @ B[K,N], f32x2 packed ------------------
// 128x64 tile, 256 threads, each thread 8(M)x4(N) accumulators packed as 4x4 f32x2.
__global__ void sgemm_f32x2(const float* __restrict__ A, const float* __restrict__ B,
                            float* __restrict__ C, int M, int N, int K) {
    __shared__ float As[16][128];
    __shared__ float Bs[16][64];
    int tid = threadIdx.x;
    int tx = tid & 15, ty = tid >> 4;
    int rowBase = blockIdx.y * 128, colBase = blockIdx.x * 64;
    ull acc[4][4];
#pragma unroll
    for (int i = 0; i < 4; i++)
#pragma unroll
        for (int j = 0; j < 4; j++) acc[i][j] = 0ull;

    for (int k0 = 0; k0 < K; k0 += 16) {
#pragma unroll
        for (int i = 0; i < 8; i++) {
            int idx = tid + i * 256;
            int r = idx >> 4, c = idx & 15;
            int gr = rowBase + r;
            As[c][r] = (gr < M) ? A[(size_t)gr * K + k0 + c] : 0.f;
        }
#pragma unroll
        for (int i = 0; i < 4; i++) {
            int idx = tid + i * 256;
            int r = idx >> 6, c = idx & 63;
            Bs[r][c] = B[(size_t)(k0 + r) * N + colBase + c];
        }
        __syncthreads();
#pragma unroll
        for (int k = 0; k < 16; k++) {
            ull ap[4];
#pragma unroll
            for (int mp = 0; mp < 4; mp++)
                ap[mp] = *(const ull*)&As[k][ty * 8 + 2 * mp];
            float4 bv = *(const float4*)&Bs[k][tx * 4];
            ull bd0, bd1, bd2, bd3;
            PACK2(bd0, bv.x); PACK2(bd1, bv.y); PACK2(bd2, bv.z); PACK2(bd3, bv.w);
#pragma unroll
            for (int mp = 0; mp < 4; mp++) {
                FMA2(acc[mp][0], ap[mp], bd0);
                FMA2(acc[mp][1], ap[mp], bd1);
                FMA2(acc[mp][2], ap[mp], bd2);
                FMA2(acc[mp][3], ap[mp], bd3);
            }
        }
        __syncthreads();
    }
#pragma unroll
    for (int mp = 0; mp < 4; mp++) {
        int r0 = rowBase + ty * 8 + 2 * mp;
#pragma unroll
        for (int n = 0; n < 4; n++) {
            unsigned lo, hi;
            UNPACK2(lo, hi, acc[mp][n]);
            int col = colBase + tx * 4 + n;
            if (r0 < M)     C[(size_t)r0 * N + col]       = __uint_as_float(lo);
            if (r0 + 1 < M) C[(size_t)(r0 + 1) * N + col] = __uint_as_float(hi);
        }
    }
}

// ---------------- attention dots: warp per (node*head) --------------------------
__global__ void attn_dots(const float* __restrict__ xh, const float* __restrict__ asrc,
                          const float* __restrict__ adst, float* __restrict__ als,
                          float* __restrict__ ald, int NH, int H) {
    int w = (blockIdx.x * blockDim.x + threadIdx.x) >> 5;
    if (w >= NH) return;
    int lane = threadIdx.x & 31;
    int h = w % H;
    const float* row = xh + (size_t)w * 64;
    float x0 = row[lane], x1 = row[lane + 32];
    float s = x0 * asrc[h * 64 + lane] + x1 * asrc[h * 64 + lane + 32];
    float d = x0 * adst[h * 64 + lane] + x1 * adst[h * 64 + lane + 32];
#pragma unroll
    for (int o = 16; o; o >>= 1) {
        s += __shfl_down_sync(0xFFFFFFFFu, s, o);
        d += __shfl_down_sync(0xFFFFFFFFu, d, o);
    }
    if (lane == 0) { als[w] = s; ald[w] = d; }
}

// ---------------- fused layer-1 aggregation (H=4, C=64) -------------------------
// warp per dst node: softmax over CSR in-edges + weighted gather + bias + ELU
__global__ void agg_fused1(const float* __restrict__ als, const float* __restrict__ ald,
                           const float* __restrict__ xh, const float* __restrict__ bias,
                           float* __restrict__ hout) {
    int node = (blockIdx.x * blockDim.x + threadIdx.x) >> 5;
    if (node >= NV) return;
    int lane = threadIdx.x & 31;
    int beg = g_rowptr[node], end = g_rowptr[node + 1];
    float4 aldv = *(const float4*)&ald[node * 4];

    // pass A: per-head max
    float m0 = -1e30f, m1 = -1e30f, m2 = -1e30f, m3 = -1e30f;
    for (int j = beg + lane; j < end; j += 32) {
        int s = g_elist[j];
        float4 a = *(const float4*)&als[s * 4];
        m0 = fmaxf(m0, lrelu(a.x + aldv.x));
        m1 = fmaxf(m1, lrelu(a.y + aldv.y));
        m2 = fmaxf(m2, lrelu(a.z + aldv.z));
        m3 = fmaxf(m3, lrelu(a.w + aldv.w));
    }
#pragma unroll
    for (int o = 16; o; o >>= 1) {
        m0 = fmaxf(m0, __shfl_xor_sync(0xFFFFFFFFu, m0, o));
        m1 = fmaxf(m1, __shfl_xor_sync(0xFFFFFFFFu, m1, o));
        m2 = fmaxf(m2, __shfl_xor_sync(0xFFFFFFFFu, m2, o));
        m3 = fmaxf(m3, __shfl_xor_sync(0xFFFFFFFFu, m3, o));
    }
    // pass B: denominator
    float d0 = 0.f, d1 = 0.f, d2 = 0.f, d3 = 0.f;
    for (int j = beg + lane; j < end; j += 32) {
        int s = g_elist[j];
        float4 a = *(const float4*)&als[s * 4];
        d0 += expf(lrelu(a.x + aldv.x) - m0);
        d1 += expf(lrelu(a.y + aldv.y) - m1);
        d2 += expf(lrelu(a.z + aldv.z) - m2);
        d3 += expf(lrelu(a.w + aldv.w) - m3);
    }
#pragma unroll
    for (int o = 16; o; o >>= 1) {
        d0 += __shfl_xor_sync(0xFFFFFFFFu, d0, o);
        d1 += __shfl_xor_sync(0xFFFFFFFFu, d1, o);
        d2 += __shfl_xor_sync(0xFFFFFFFFu, d2, o);
        d3 += __shfl_xor_sync(0xFFFFFFFFu, d3, o);
    }
    float i0 = 1.f / (d0 + 1e-16f), i1 = 1.f / (d1 + 1e-16f);
    float i2 = 1.f / (d2 + 1e-16f), i3 = 1.f / (d3 + 1e-16f);

    // per-lane head selection: lane handles columns [lane*8, lane*8+8) => head = lane>>3
    int myh = lane >> 3;
    float mym   = myh == 0 ? m0 : myh == 1 ? m1 : myh == 2 ? m2 : m3;
    float myinv = myh == 0 ? i0 : myh == 1 ? i1 : myh == 2 ? i2 : i3;
    float myald = myh == 0 ? aldv.x : myh == 1 ? aldv.y : myh == 2 ? aldv.z : aldv.w;

    float acc[8] = {0.f, 0.f, 0.f, 0.f, 0.f, 0.f, 0.f, 0.f};
    for (int j0 = beg; j0 < end; j0 += 32) {
        int sv = (j0 + lane < end) ? g_elist[j0 + lane] : 0;
        int cnt = min(32, end - j0);
        for (int k = 0; k < cnt; k++) {
            int s = __shfl_sync(0xFFFFFFFFu, sv, k);
            float w = expf(lrelu(als[s * 4 + myh] + myald) - mym) * myinv;
            const float4* r = (const float4*)(xh + (size_t)s * 256 + lane * 8);
            float4 p = r[0], q = r[1];
            acc[0] += w * p.x; acc[1] += w * p.y; acc[2] += w * p.z; acc[3] += w * p.w;
            acc[4] += w * q.x; acc[5] += w * q.y; acc[6] += w * q.z; acc[7] += w * q.w;
        }
    }
    // epilogue: h = elu(acc + bias)
    int c = lane * 8;
    float4 o0, o1;
    float* po = (float*)&o0;
#pragma unroll
    for (int i = 0; i < 4; i++) {
        float v = acc[i] + bias[c + i];
        po[i] = v > 0.f ? v : expm1f(v);
    }
    po = (float*)&o1;
#pragma unroll
    for (int i = 0; i < 4; i++) {
        float v = acc[4 + i] + bias[c + 4 + i];
        po[i] = v > 0.f ? v : expm1f(v);
    }
    *(float4*)(hout + (size_t)node * 256 + c)     = o0;
    *(float4*)(hout + (size_t)node * 256 + c + 4) = o1;
}

// ---------------- fused layer-2 aggregation (H=1, C=64) -------------------------
__global__ void agg_fused2(const float* __restrict__ als, const float* __restrict__ ald,
                           const float* __restrict__ xh, const float* __restrict__ bias,
                           float* __restrict__ out) {
    int node = (blockIdx.x * blockDim.x + threadIdx.x) >> 5;
    if (node >= NV) return;
    int lane = threadIdx.x & 31;
    int beg = g_rowptr[node], end = g_rowptr[node + 1];
    float aldv = ald[node];

    float m = -1e30f;
    for (int j = beg + lane; j < end; j += 32) {
        int s = g_elist[j];
        m = fmaxf(m, lrelu(als[s] + aldv));
    }
#pragma unroll
    for (int o = 16; o; o >>= 1) m = fmaxf(m, __shfl_xor_sync(0xFFFFFFFFu, m, o));

    float den = 0.f;
    for (int j = beg + lane; j < end; j += 32) {
        int s = g_elist[j];
        den += expf(lrelu(als[s] + aldv) - m);
    }
#pragma unroll
    for (int o = 16; o; o >>= 1) den += __shfl_xor_sync(0xFFFFFFFFu, den, o);
    float inv = 1.f / (den + 1e-16f);

    float a0 = 0.f, a1 = 0.f;
    for (int j0 = beg; j0 < end; j0 += 32) {
        int sv = (j0 + lane < end) ? g_elist[j0 + lane] : 0;
        int cnt = min(32, end - j0);
        for (int k = 0; k < cnt; k++) {
            int s = __shfl_sync(0xFFFFFFFFu, sv, k);
            float w = expf(lrelu(als[s] + aldv) - m) * inv;
            float2 p = *(const float2*)(xh + (size_t)s * 64 + lane * 2);
            a0 += w * p.x; a1 += w * p.y;
        }
    }
    int c = lane * 2;
    float v0 = a0 + bias[c],     r0 = v0 > 0.f ? v0 : expm1f(v0);
    float v1 = a1 + bias[c + 1], r1 = v1 > 0.f ? v1 : expm1f(v1);
    *(float2*)(out + (size_t)node * 64 + c) = make_float2(r0, r1);
}

// ---------------- launch ---------------------------------------------------------
extern "C" void kernel_launch(void* const* d_in, const int* in_sizes, int n_in,
                              void* d_out, int out_size) {
    const float* x     = (const float*)d_in[0];
    const int*   ei    = (const int*)d_in[1];
    const float* W1    = (const float*)d_in[2];
    const float* asrc1 = (const float*)d_in[3];
    const float* adst1 = (const float*)d_in[4];
    const float* b1    = (const float*)d_in[5];
    const float* W2    = (const float*)d_in[6];
    const float* asrc2 = (const float*)d_in[7];
    const float* adst2 = (const float*)d_in[8];
    const float* b2    = (const float*)d_in[9];
    float* out = (float*)d_out;

    float *xh1, *h1, *xh2, *als1, *ald1, *als2, *ald2;
    cudaGetSymbolAddress((void**)&xh1,  g_xh1);
    cudaGetSymbolAddress((void**)&h1,   g_h1);
    cudaGetSymbolAddress((void**)&xh2,  g_xh2);
    cudaGetSymbolAddress((void**)&als1, g_als1);
    cudaGetSymbolAddress((void**)&ald1, g_ald1);
    cudaGetSymbolAddress((void**)&als2, g_als2);
    cudaGetSymbolAddress((void**)&ald2, g_ald2);

    const int TB = 256;

    // ----- CSR build (shared by both layers) -----
    deg_init<<<(NV + TB - 1) / TB, TB>>>();
    deg_hist<<<(EE + TB - 1) / TB, TB>>>(ei);
    scan_k<<<1, 1024>>>();
    scatter_k<<<(ET + TB - 1) / TB, TB>>>(ei);

    // ----- layer 1 -----
    {
        dim3 grid(D1 / 64, (NV + 127) / 128);
        sgemm_f32x2<<<grid, 256>>>(x, W1, xh1, NV, D1, FIN);
    }
    attn_dots<<<(NV * HEADS * 32 + TB - 1) / TB, TB>>>(xh1, asrc1, adst1, als1, ald1, NV * HEADS, HEADS);
    agg_fused1<<<(NV * 32 + TB - 1) / TB, TB>>>(als1, ald1, xh1, b1, h1);

    // ----- layer 2 -----
    {
        dim3 grid(1, (NV + 127) / 128);
        sgemm_f32x2<<<grid, 256>>>(h1, W2, xh2, NV, HID, D1);
    }
    attn_dots<<<(NV * 32 + TB - 1) / TB, TB>>>(xh2, asrc2, adst2, als2, ald2, NV, 1);
    agg_fused2<<<(NV * 32 + TB - 1) / TB, TB>>>(als2, ald2, xh2, b2, out);
}

// round 3
// speedup vs baseline: 1.4318x; 1.0609x over previous
#include <cuda_runtime.h>
#include <cuda_bf16.h>
#include <math.h>

#define NV 50000
#define EE 800000
#define ET (EE + NV)        // edges incl. self loops
#define FIN 256
#define HID 64
#define HEADS 4
#define D1 (HEADS * HID)    // 256

typedef unsigned long long ull;

// ---------------- scratch -----------------------------------------------------
__device__ float g_xh1[NV * D1];
__device__ float g_h1[NV * D1];
__device__ float g_xh2[NV * HID];
__device__ float g_als1[NV * HEADS];
__device__ float g_ald1[NV * HEADS];
__device__ float g_als2[NV];
__device__ float g_ald2[NV];
__device__ float g_inv1[NV * HEADS];
__device__ float g_inv2[NV];
__device__ float g_t1[ET * HEADS];   // unnormalized exp per CSR slot (layer1, 4 heads)
__device__ float g_t2[ET];           // layer2
__device__ int   g_rowptr[NV + 1];
__device__ int   g_deg[NV];          // degree -> cursor
__device__ int   g_elist[ET];        // src node per CSR slot

// ---------------- helpers ------------------------------------------------------
__device__ __forceinline__ float lrelu(float v) { return v > 0.f ? v : 0.2f * v; }

__device__ __forceinline__ void edge_sd(const int* __restrict__ ei, int e, int& s, int& d) {
    if (e < EE) { s = ei[e]; d = ei[EE + e]; }
    else        { s = e - EE; d = s; }
}

#define FMA2(acc, a, b) asm("fma.rn.f32x2 %0, %1, %2, %3;" : "=l"(acc) : "l"(a), "l"(b), "l"(acc))
#define PACK2(out, v)   asm("mov.b64 %0, {%1, %1};" : "=l"(out) : "r"(__float_as_uint(v)))
#define UNPACK2(lo, hi, in) asm("mov.b64 {%0, %1}, %2;" : "=r"(lo), "=r"(hi) : "l"(in))

// ---------------- CSR build ----------------------------------------------------
__global__ void deg_init() {
    int i = blockIdx.x * blockDim.x + threadIdx.x;
    if (i < NV) g_deg[i] = 1;   // self loop
}
__global__ void deg_hist(const int* __restrict__ ei) {
    int e = blockIdx.x * blockDim.x + threadIdx.x;
    if (e < EE) atomicAdd(&g_deg[ei[EE + e]], 1);
}
__global__ void scan_k() {
    __shared__ int ssum[1024];
    const int CH = (NV + 1023) / 1024;
    int t = threadIdx.x;
    int base = t * CH;
    int s = 0;
    for (int j = 0; j < CH; j++) { int i = base + j; if (i < NV) s += g_deg[i]; }
    ssum[t] = s;
    __syncthreads();
    for (int off = 1; off < 1024; off <<= 1) {
        int v = (t >= off) ? ssum[t - off] : 0;
        __syncthreads();
        ssum[t] += v;
        __syncthreads();
    }
    int off = (t == 0) ? 0 : ssum[t - 1];
    for (int j = 0; j < CH; j++) {
        int i = base + j;
        if (i < NV) {
            int d = g_deg[i];
            g_rowptr[i] = off;
            g_deg[i] = off;   // cursor
            off += d;
        }
    }
    if (t == 0) g_rowptr[NV] = ET;
}
__global__ void scatter_k(const int* __restrict__ ei) {
    int e = blockIdx.x * blockDim.x + threadIdx.x;
    if (e >= ET) return;
    int s, d; edge_sd(ei, e, s, d);
    int pos = atomicAdd(&g_deg[d], 1);
    g_elist[pos] = s;
}

// ---------------- GEMM A: 128x128 tile, 8x8 micro, f32x2 ------------------------
// C[M,N] = A[M,K] @ B[K,N]. N multiple of 128, K multiple of 8.
__global__ void sgemm128(const float* __restrict__ A, const float* __restrict__ B,
                         float* __restrict__ C, int M, int N, int K) {
    __shared__ float As[8][128];   // As[k][m]
    __shared__ float Bs[8][128];   // Bs[k][n]
    int tid = threadIdx.x;
    int tx = tid & 15, ty = tid >> 4;
    int rowBase = blockIdx.y * 128, colBase = blockIdx.x * 128;
    int m0 = ty * 8, n0 = tx * 8;

    // load indices
    int arow = tid >> 1;            // 0..127
    int akc  = (tid & 1) * 4;       // 0 or 4
    int brow = tid >> 5;            // 0..7
    int bcol = (tid & 31) * 4;      // 0..124

    ull acc[4][8];
#pragma unroll
    for (int i = 0; i < 4; i++)
#pragma unroll
        for (int j = 0; j < 8; j++) acc[i][j] = 0ull;

    for (int k0 = 0; k0 < K; k0 += 8) {
        // A tile: 128 rows x 8 k
        {
            int gr = rowBase + arow;
            float4 a4 = make_float4(0.f, 0.f, 0.f, 0.f);
            if (gr < M) a4 = *(const float4*)&A[(size_t)gr * K + k0 + akc];
            As[akc + 0][arow] = a4.x;
            As[akc + 1][arow] = a4.y;
            As[akc + 2][arow] = a4.z;
            As[akc + 3][arow] = a4.w;
        }
        // B tile: 8 rows x 128 cols
        {
            float4 b4 = *(const float4*)&B[(size_t)(k0 + brow) * N + colBase + bcol];
            *(float4*)&Bs[brow][bcol] = b4;
        }
        __syncthreads();
#pragma unroll
        for (int k = 0; k < 8; k++) {
            ull ap[4];
            const ull* pa = (const ull*)&As[k][m0];
#pragma unroll
            for (int i = 0; i < 4; i++) ap[i] = pa[i];
            float4 b0 = *(const float4*)&Bs[k][n0];
            float4 b1 = *(const float4*)&Bs[k][n0 + 4];
            ull bd[8];
            PACK2(bd[0], b0.x); PACK2(bd[1], b0.y); PACK2(bd[2], b0.z); PACK2(bd[3], b0.w);
            PACK2(bd[4], b1.x); PACK2(bd[5], b1.y); PACK2(bd[6], b1.z); PACK2(bd[7], b1.w);
#pragma unroll
            for (int mp = 0; mp < 4; mp++)
#pragma unroll
                for (int n = 0; n < 8; n++) FMA2(acc[mp][n], ap[mp], bd[n]);
        }
        __syncthreads();
    }
    // epilogue: 8 rows x 8 cols per thread
#pragma unroll
    for (int mp = 0; mp < 4; mp++) {
        int r0 = rowBase + m0 + 2 * mp;
        float lo[8], hi[8];
#pragma unroll
        for (int n = 0; n < 8; n++) {
            unsigned l, h;
            UNPACK2(l, h, acc[mp][n]);
            lo[n] = __uint_as_float(l);
            hi[n] = __uint_as_float(h);
        }
        int col = colBase + n0;
        if (r0 < M) {
            *(float4*)&C[(size_t)r0 * N + col]     = *(float4*)&lo[0];
            *(float4*)&C[(size_t)r0 * N + col + 4] = *(float4*)&lo[4];
        }
        if (r0 + 1 < M) {
            *(float4*)&C[(size_t)(r0 + 1) * N + col]     = *(float4*)&hi[0];
            *(float4*)&C[(size_t)(r0 + 1) * N + col + 4] = *(float4*)&hi[4];
        }
    }
}

// ---------------- GEMM B: 128x64 tile, 8x4 micro, f32x2 (for layer 2) ----------
__global__ void sgemm64(const float* __restrict__ A, const float* __restrict__ B,
                        float* __restrict__ C, int M, int N, int K) {
    __shared__ float As[16][128];
    __shared__ float Bs[16][64];
    int tid = threadIdx.x;
    int tx = tid & 15, ty = tid >> 4;
    int rowBase = blockIdx.y * 128, colBase = blockIdx.x * 64;
    ull acc[4][4];
#pragma unroll
    for (int i = 0; i < 4; i++)
#pragma unroll
        for (int j = 0; j < 4; j++) acc[i][j] = 0ull;

    for (int k0 = 0; k0 < K; k0 += 16) {
#pragma unroll
        for (int i = 0; i < 8; i++) {
            int idx = tid + i * 256;
            int r = idx >> 4, c = idx & 15;
            int gr = rowBase + r;
            As[c][r] = (gr < M) ? A[(size_t)gr * K + k0 + c] : 0.f;
        }
#pragma unroll
        for (int i = 0; i < 4; i++) {
            int idx = tid + i * 256;
            int r = idx >> 6, c = idx & 63;
            Bs[r][c] = B[(size_t)(k0 + r) * N + colBase + c];
        }
        __syncthreads();
#pragma unroll
        for (int k = 0; k < 16; k++) {
            ull ap[4];
            const ull* pa = (const ull*)&As[k][ty * 8];
#pragma unroll
            for (int mp = 0; mp < 4; mp++) ap[mp] = pa[mp];
            float4 bv = *(const float4*)&Bs[k][tx * 4];
            ull bd0, bd1, bd2, bd3;
            PACK2(bd0, bv.x); PACK2(bd1, bv.y); PACK2(bd2, bv.z); PACK2(bd3, bv.w);
#pragma unroll
            for (int mp = 0; mp < 4; mp++) {
                FMA2(acc[mp][0], ap[mp], bd0);
                FMA2(acc[mp][1], ap[mp], bd1);
                FMA2(acc[mp][2], ap[mp], bd2);
                FMA2(acc[mp][3], ap[mp], bd3);
            }
        }
        __syncthreads();
    }
#pragma unroll
    for (int mp = 0; mp < 4; mp++) {
        int r0 = rowBase + ty * 8 + 2 * mp;
#pragma unroll
        for (int n = 0; n < 4; n++) {
            unsigned lo, hi;
            UNPACK2(lo, hi, acc[mp][n]);
            int col = colBase + tx * 4 + n;
            if (r0 < M)     C[(size_t)r0 * N + col]       = __uint_as_float(lo);
            if (r0 + 1 < M) C[(size_t)(r0 + 1) * N + col] = __uint_as_float(hi);
        }
    }
}

// ---------------- attention dots: warp per (node*head) --------------------------
__global__ void attn_dots(const float* __restrict__ xh, const float* __restrict__ asrc,
                          const float* __restrict__ adst, float* __restrict__ als,
                          float* __restrict__ ald, int NH, int H) {
    int w = (blockIdx.x * blockDim.x + threadIdx.x) >> 5;
    if (w >= NH) return;
    int lane = threadIdx.x & 31;
    int h = w % H;
    const float* row = xh + (size_t)w * 64;
    float x0 = row[lane], x1 = row[lane + 32];
    float s = x0 * asrc[h * 64 + lane] + x1 * asrc[h * 64 + lane + 32];
    float d = x0 * adst[h * 64 + lane] + x1 * adst[h * 64 + lane + 32];
#pragma unroll
    for (int o = 16; o; o >>= 1) {
        s += __shfl_down_sync(0xFFFFFFFFu, s, o);
        d += __shfl_down_sync(0xFFFFFFFFu, d, o);
    }
    if (lane == 0) { als[w] = s; ald[w] = d; }
}

// ---------------- softmax layer1: warp per node ----------------------------------
// computes t[j] = exp(lrelu(als[s]+ald[d]) - m) per slot and inv = 1/den per node/head
__global__ void soft1(const float* __restrict__ als, const float* __restrict__ ald) {
    int node = (blockIdx.x * blockDim.x + threadIdx.x) >> 5;
    if (node >= NV) return;
    int lane = threadIdx.x & 31;
    int beg = g_rowptr[node], end = g_rowptr[node + 1];
    float4 aldv = *(const float4*)&ald[node * 4];

    float m0 = -1e30f, m1 = -1e30f, m2 = -1e30f, m3 = -1e30f;
    for (int j = beg + lane; j < end; j += 32) {
        int s = g_elist[j];
        float4 a = *(const float4*)&als[s * 4];
        m0 = fmaxf(m0, lrelu(a.x + aldv.x));
        m1 = fmaxf(m1, lrelu(a.y + aldv.y));
        m2 = fmaxf(m2, lrelu(a.z + aldv.z));
        m3 = fmaxf(m3, lrelu(a.w + aldv.w));
    }
#pragma unroll
    for (int o = 16; o; o >>= 1) {
        m0 = fmaxf(m0, __shfl_xor_sync(0xFFFFFFFFu, m0, o));
        m1 = fmaxf(m1, __shfl_xor_sync(0xFFFFFFFFu, m1, o));
        m2 = fmaxf(m2, __shfl_xor_sync(0xFFFFFFFFu, m2, o));
        m3 = fmaxf(m3, __shfl_xor_sync(0xFFFFFFFFu, m3, o));
    }
    float d0 = 0.f, d1 = 0.f, d2 = 0.f, d3 = 0.f;
    for (int j = beg + lane; j < end; j += 32) {
        int s = g_elist[j];
        float4 a = *(const float4*)&als[s * 4];
        float t0 = expf(lrelu(a.x + aldv.x) - m0);
        float t1 = expf(lrelu(a.y + aldv.y) - m1);
        float t2 = expf(lrelu(a.z + aldv.z) - m2);
        float t3 = expf(lrelu(a.w + aldv.w) - m3);
        *(float4*)&g_t1[(size_t)j * 4] = make_float4(t0, t1, t2, t3);
        d0 += t0; d1 += t1; d2 += t2; d3 += t3;
    }
#pragma unroll
    for (int o = 16; o; o >>= 1) {
        d0 += __shfl_xor_sync(0xFFFFFFFFu, d0, o);
        d1 += __shfl_xor_sync(0xFFFFFFFFu, d1, o);
        d2 += __shfl_xor_sync(0xFFFFFFFFu, d2, o);
        d3 += __shfl_xor_sync(0xFFFFFFFFu, d3, o);
    }
    if (lane == 0) {
        *(float4*)&g_inv1[node * 4] = make_float4(
            1.f / (d0 + 1e-16f), 1.f / (d1 + 1e-16f),
            1.f / (d2 + 1e-16f), 1.f / (d3 + 1e-16f));
    }
}

// ---------------- gather layer1: warp per node, f32x2 accumulate ----------------
__global__ void gather1(const float* __restrict__ xh, const float* __restrict__ bias,
                        float* __restrict__ hout) {
    int node = (blockIdx.x * blockDim.x + threadIdx.x) >> 5;
    if (node >= NV) return;
    int lane = threadIdx.x & 31;
    int beg = g_rowptr[node], end = g_rowptr[node + 1];
    int myh = lane >> 3;
    float myinv = g_inv1[node * 4 + myh];

    ull acc[4] = {0ull, 0ull, 0ull, 0ull};
    for (int j0 = beg; j0 < end; j0 += 32) {
        int sv = (j0 + lane < end) ? g_elist[j0 + lane] : 0;
        int cnt = min(32, end - j0);
        for (int k = 0; k < cnt; k++) {
            int s = __shfl_sync(0xFFFFFFFFu, sv, k);
            float w = g_t1[(size_t)(j0 + k) * 4 + myh] * myinv;
            ull wd; PACK2(wd, w);
            const ull* r = (const ull*)(xh + (size_t)s * 256 + lane * 8);
            FMA2(acc[0], r[0], wd);
            FMA2(acc[1], r[1], wd);
            FMA2(acc[2], r[2], wd);
            FMA2(acc[3], r[3], wd);
        }
    }
    int c = lane * 8;
    float o[8];
#pragma unroll
    for (int i = 0; i < 4; i++) {
        unsigned lo, hi;
        UNPACK2(lo, hi, acc[i]);
        float v0 = __uint_as_float(lo) + bias[c + 2 * i];
        float v1 = __uint_as_float(hi) + bias[c + 2 * i + 1];
        o[2 * i]     = v0 > 0.f ? v0 : expm1f(v0);
        o[2 * i + 1] = v1 > 0.f ? v1 : expm1f(v1);
    }
    *(float4*)(hout + (size_t)node * 256 + c)     = *(float4*)&o[0];
    *(float4*)(hout + (size_t)node * 256 + c + 4) = *(float4*)&o[4];
}

// ---------------- softmax layer2 --------------------------------------------------
__global__ void soft2(const float* __restrict__ als, const float* __restrict__ ald) {
    int node = (blockIdx.x * blockDim.x + threadIdx.x) >> 5;
    if (node >= NV) return;
    int lane = threadIdx.x & 31;
    int beg = g_rowptr[node], end = g_rowptr[node + 1];
    float aldv = ald[node];

    float m = -1e30f;
    for (int j = beg + lane; j < end; j += 32) {
        int s = g_elist[j];
        m = fmaxf(m, lrelu(als[s] + aldv));
    }
#pragma unroll
    for (int o = 16; o; o >>= 1) m = fmaxf(m, __shfl_xor_sync(0xFFFFFFFFu, m, o));

    float den = 0.f;
    for (int j = beg + lane; j < end; j += 32) {
        int s = g_elist[j];
        float t = expf(lrelu(als[s] + aldv) - m);
        g_t2[j] = t;
        den += t;
    }
#pragma unroll
    for (int o = 16; o; o >>= 1) den += __shfl_xor_sync(0xFFFFFFFFu, den, o);
    if (lane == 0) g_inv2[node] = 1.f / (den + 1e-16f);
}

// ---------------- gather layer2 ----------------------------------------------------
__global__ void gather2(const float* __restrict__ xh, const float* __restrict__ bias,
                        float* __restrict__ out) {
    int node = (blockIdx.x * blockDim.x + threadIdx.x) >> 5;
    if (node >= NV) return;
    int lane = threadIdx.x & 31;
    int beg = g_rowptr[node], end = g_rowptr[node + 1];
    float inv = g_inv2[node];

    ull acc = 0ull;
    for (int j0 = beg; j0 < end; j0 += 32) {
        int idx = j0 + lane;
        int sv = (idx < end) ? g_elist[idx] : 0;
        float tv = (idx < end) ? g_t2[idx] : 0.f;
        int cnt = min(32, end - j0);
        for (int k = 0; k < cnt; k++) {
            int s = __shfl_sync(0xFFFFFFFFu, sv, k);
            float w = __shfl_sync(0xFFFFFFFFu, tv, k) * inv;
            ull wd; PACK2(wd, w);
            ull r = *(const ull*)(xh + (size_t)s * 64 + lane * 2);
            FMA2(acc, r, wd);
        }
    }
    int c = lane * 2;
    unsigned lo, hi;
    UNPACK2(lo, hi, acc);
    float v0 = __uint_as_float(lo) + bias[c];
    float v1 = __uint_as_float(hi) + bias[c + 1];
    float r0 = v0 > 0.f ? v0 : expm1f(v0);
    float r1 = v1 > 0.f ? v1 : expm1f(v1);
    *(float2*)(out + (size_t)node * 64 + c) = make_float2(r0, r1);
}

// ---------------- launch ---------------------------------------------------------
extern "C" void kernel_launch(void* const* d_in, const int* in_sizes, int n_in,
                              void* d_out, int out_size) {
    const float* x     = (const float*)d_in[0];
    const int*   ei    = (const int*)d_in[1];
    const float* W1    = (const float*)d_in[2];
    const float* asrc1 = (const float*)d_in[3];
    const float* adst1 = (const float*)d_in[4];
    const float* b1    = (const float*)d_in[5];
    const float* W2    = (const float*)d_in[6];
    const float* asrc2 = (const float*)d_in[7];
    const float* adst2 = (const float*)d_in[8];
    const float* b2    = (const float*)d_in[9];
    float* out = (float*)d_out;

    float *xh1, *h1, *xh2, *als1, *ald1, *als2, *ald2;
    cudaGetSymbolAddress((void**)&xh1,  g_xh1);
    cudaGetSymbolAddress((void**)&h1,   g_h1);
    cudaGetSymbolAddress((void**)&xh2,  g_xh2);
    cudaGetSymbolAddress((void**)&als1, g_als1);
    cudaGetSymbolAddress((void**)&ald1, g_ald1);
    cudaGetSymbolAddress((void**)&als2, g_als2);
    cudaGetSymbolAddress((void**)&ald2, g_ald2);

    const int TB = 256;

    // ----- CSR build -----
    deg_init<<<(NV + TB - 1) / TB, TB>>>();
    deg_hist<<<(EE + TB - 1) / TB, TB>>>(ei);
    scan_k<<<1, 1024>>>();
    scatter_k<<<(ET + TB - 1) / TB, TB>>>(ei);

    // ----- layer 1 -----
    {
        dim3 grid(D1 / 128, (NV + 127) / 128);
        sgemm128<<<grid, 256>>>(x, W1, xh1, NV, D1, FIN);
    }
    attn_dots<<<(NV * HEADS * 32 + TB - 1) / TB, TB>>>(xh1, asrc1, adst1, als1, ald1, NV * HEADS, HEADS);
    soft1<<<(NV * 32 + TB - 1) / TB, TB>>>(als1, ald1);
    gather1<<<(NV * 32 + TB - 1) / TB, TB>>>(xh1, b1, h1);

    // ----- layer 2 -----
    {
        dim3 grid(1, (NV + 127) / 128);
        sgemm64<<<grid, 256>>>(h1, W2, xh2, NV, HID, D1);
    }
    attn_dots<<<(NV * 32 + TB - 1) / TB, TB>>>(xh2, asrc2, adst2, als2, ald2, NV, 1);
    soft2<<<(NV * 32 + TB - 1) / TB, TB>>>(als2, ald2);
    gather2<<<(NV * 32 + TB - 1) / TB, TB>>>(xh2, b2, out);
}